// round 7
// baseline (speedup 1.0000x reference)
#include <cuda_runtime.h>
#include <cuda_bf16.h>
#include <cstdint>

#define BB 4
#define TT 4096
#define CCH 1024
#define MTOT (BB*TT)
#define NELEM (MTOT*CCH)
#define NCHUNK 32
#define CHUNK_L (TT/NCHUNK)

// GEMM tiling: CTA 128x128, K_TILE 32, 256 threads = 8 warps (2M x 4N), warp 64x32
#define KT 32
#define ROWPAD 40                  // bf16 elems per smem row (80 bytes)
#define ARR_BYTES (128*ROWPAD*2)   // 10240
#define STAGE_BYTES (4*ARR_BYTES)  // 40960
#define GEMM_SMEM (2*STAGE_BYTES)  // 81920

// ---------- scratch ----------
__device__ __nv_bfloat16 g_rin_h[NELEM], g_rin_l[NELEM];
__device__ __nv_bfloat16 g_kin_h[NELEM], g_kin_l[NELEM];
__device__ __nv_bfloat16 g_vin_h[NELEM], g_vin_l[NELEM];
__device__ float g_r[NELEM], g_k[NELEM], g_v[NELEM];
__device__ __nv_bfloat16 g_oh[NELEM], g_ol[NELEM];
__device__ __nv_bfloat16 g_Wr_h[CCH*CCH], g_Wr_l[CCH*CCH];
__device__ __nv_bfloat16 g_Wk_h[CCH*CCH], g_Wk_l[CCH*CCH];
__device__ __nv_bfloat16 g_Wv_h[CCH*CCH], g_Wv_l[CCH*CCH];
__device__ __nv_bfloat16 g_Wo_h[CCH*CCH], g_Wo_l[CCH*CCH];
__device__ float g_carry[BB*NCHUNK*CCH];
__device__ float g_sin[BB*NCHUNK*CCH];

// ---------- helpers ----------
static __device__ __forceinline__ uint32_t smem_u32(const void* p){
    uint32_t a;
    asm("{ .reg .u64 t; cvta.to.shared.u64 t, %1; cvt.u32.u64 %0, t; }" : "=r"(a) : "l"(p));
    return a;
}
static __device__ __forceinline__ void cp16(uint32_t s, const void* g){
    asm volatile("cp.async.cg.shared.global [%0], [%1], 16;" :: "r"(s), "l"(g) : "memory");
}
#define CP_COMMIT() asm volatile("cp.async.commit_group;" ::: "memory")
#define CP_WAIT(n)  asm volatile("cp.async.wait_group %0;" :: "n"(n) : "memory")

#define LDSM4(r0,r1,r2,r3,a) \
    asm volatile("ldmatrix.sync.aligned.m8n8.x4.shared.b16 {%0,%1,%2,%3}, [%4];" \
        : "=r"(r0),"=r"(r1),"=r"(r2),"=r"(r3) : "r"(a))
#define LDSM2(r0,r1,a) \
    asm volatile("ldmatrix.sync.aligned.m8n8.x2.shared.b16 {%0,%1}, [%2];" \
        : "=r"(r0),"=r"(r1) : "r"(a))

#define MMA16816(c, a, b) \
    asm volatile("mma.sync.aligned.m16n8k16.row.col.f32.bf16.bf16.f32 " \
        "{%0,%1,%2,%3}, {%4,%5,%6,%7}, {%8,%9}, {%0,%1,%2,%3};" \
        : "+f"((c)[0]),"+f"((c)[1]),"+f"((c)[2]),"+f"((c)[3]) \
        : "r"((a)[0]),"r"((a)[1]),"r"((a)[2]),"r"((a)[3]), "r"((b)[0]),"r"((b)[1]))

static __device__ __forceinline__ void split2(float v, __nv_bfloat16& h, __nv_bfloat16& l){
    h = __float2bfloat16(v);
    l = __float2bfloat16(v - __bfloat162float(h));
}

// ---------- prep ----------
__global__ void split_w_k(const float* __restrict__ w, __nv_bfloat16* __restrict__ h,
                          __nv_bfloat16* __restrict__ l){
    int i = blockIdx.x * 256 + threadIdx.x;
    __nv_bfloat16 a, b; split2(w[i], a, b); h[i] = a; l[i] = b;
}
__global__ void prep_k(const float* __restrict__ x, const float* __restrict__ st,
                       const float* __restrict__ tmr, const float* __restrict__ tmk,
                       const float* __restrict__ tmv){
    int i = blockIdx.x * 256 + threadIdx.x;
    int c = i & (CCH - 1);
    int bt = i >> 10;
    int t = bt & (TT - 1);
    float xv = x[i];
    float xm = (t == 0) ? st[(bt >> 12) * CCH + c] : x[i - CCH];
    float mr = tmr[c], mk = tmk[c], mv = tmv[c];
    __nv_bfloat16 h, l;
    split2(xv * mr + xm * (1.0f - mr), h, l); g_rin_h[i] = h; g_rin_l[i] = l;
    split2(xv * mk + xm * (1.0f - mk), h, l); g_kin_h[i] = h; g_kin_l[i] = l;
    split2(xv * mv + xm * (1.0f - mv), h, l); g_vin_h[i] = h; g_vin_l[i] = l;
}

// ---------- GEMM: out[m,n] = sum_c A[m,c]*W[n,c], split-bf16 (3 products), HMMA ----------
// smem per stage: [Ah | Al | Bh | Bl], each 128 rows x 40 bf16 (32 data + 8 pad)
static __device__ __forceinline__ void fill_stage(uint32_t st,
        const __nv_bfloat16* __restrict__ Ah, const __nv_bfloat16* __restrict__ Al,
        const __nv_bfloat16* __restrict__ Bh, const __nv_bfloat16* __restrict__ Bl,
        int m0, int n0, int k0, int tid){
    for (int idx = tid; idx < 512; idx += 256) {
        int r = idx >> 2, ch = idx & 3;
        uint32_t d = (uint32_t)(r * (ROWPAD*2) + ch * 16);
        size_t sa = (size_t)(m0 + r) * CCH + k0 + ch * 8;
        size_t sbo = (size_t)(n0 + r) * CCH + k0 + ch * 8;
        cp16(st + d,                 Ah + sa);
        cp16(st + ARR_BYTES + d,     Al + sa);
        cp16(st + 2*ARR_BYTES + d,   Bh + sbo);
        cp16(st + 3*ARR_BYTES + d,   Bl + sbo);
    }
}

__global__ void __launch_bounds__(256, 1)
gemm_split(const __nv_bfloat16* __restrict__ Ah, const __nv_bfloat16* __restrict__ Al,
           const __nv_bfloat16* __restrict__ Bh, const __nv_bfloat16* __restrict__ Bl,
           float* __restrict__ out, int act){
    extern __shared__ __align__(16) char smem[];
    uint32_t sb = smem_u32(smem);
    const int tid = threadIdx.x, lane = tid & 31, wid = tid >> 5;
    const int wm = wid >> 2, wn = wid & 3;            // 2 x 4 warp grid
    const int m0 = blockIdx.y * 128, n0 = blockIdx.x * 128;

    float acc[4][4][4];
    #pragma unroll
    for (int i = 0; i < 4; i++)
        #pragma unroll
        for (int j = 0; j < 4; j++)
            #pragma unroll
            for (int q = 0; q < 4; q++) acc[i][j][q] = 0.0f;

    fill_stage(sb,               Ah, Al, Bh, Bl, m0, n0, 0,  tid); CP_COMMIT();
    fill_stage(sb + STAGE_BYTES, Ah, Al, Bh, Bl, m0, n0, KT, tid); CP_COMMIT();

    const int NITER = CCH / KT;   // 32
    for (int ks = 0; ks < NITER; ks++) {
        uint32_t st = sb + (uint32_t)(ks & 1) * STAGE_BYTES;
        if (ks + 1 < NITER) CP_WAIT(1); else CP_WAIT(0);
        __syncthreads();

        #pragma unroll
        for (int kk = 0; kk < KT; kk += 16) {
            uint32_t ah[4][4], al[4][4], bh[4][2], bl[4][2];
            // A fragments: row = wm*64 + mt*16 + (mat&1)*8 + lane%8 ; col = kk + (mat>>1)*8
            int arow = wm * 64 + ((lane >> 3) & 1) * 8 + (lane & 7);
            int acol = kk + (lane >> 4) * 8;
            #pragma unroll
            for (int mt = 0; mt < 4; mt++) {
                uint32_t a = st + (uint32_t)((arow + mt * 16) * (ROWPAD*2) + acol * 2);
                LDSM4(ah[mt][0], ah[mt][1], ah[mt][2], ah[mt][3], a);
                LDSM4(al[mt][0], al[mt][1], al[mt][2], al[mt][3], a + ARR_BYTES);
            }
            // B fragments: row = wn*32 + nt*8 + lane%8 ; col = kk + ((lane>>3)&1)*8
            int brow = wn * 32 + (lane & 7);
            int bcol = kk + ((lane >> 3) & 1) * 8;
            #pragma unroll
            for (int nt = 0; nt < 4; nt++) {
                uint32_t b = st + 2*ARR_BYTES
                           + (uint32_t)((brow + nt * 8) * (ROWPAD*2) + bcol * 2);
                LDSM2(bh[nt][0], bh[nt][1], b);
                LDSM2(bl[nt][0], bl[nt][1], b + ARR_BYTES);
            }
            #pragma unroll
            for (int mt = 0; mt < 4; mt++)
                #pragma unroll
                for (int nt = 0; nt < 4; nt++) {
                    MMA16816(acc[mt][nt], ah[mt], bh[nt]);
                    MMA16816(acc[mt][nt], ah[mt], bl[nt]);
                    MMA16816(acc[mt][nt], al[mt], bh[nt]);
                }
        }
        __syncthreads();
        if (ks + 2 < NITER) {
            fill_stage(st, Ah, Al, Bh, Bl, m0, n0, (ks + 2) * KT, tid);
            CP_COMMIT();
        }
    }

    // epilogue with fused activation
    #pragma unroll
    for (int mt = 0; mt < 4; mt++)
        #pragma unroll
        for (int nt = 0; nt < 4; nt++) {
            int row = m0 + wm * 64 + mt * 16 + (lane >> 2);
            int col = n0 + wn * 32 + nt * 8 + (lane & 3) * 2;
            float v0 = acc[mt][nt][0], v1 = acc[mt][nt][1];
            float v2 = acc[mt][nt][2], v3 = acc[mt][nt][3];
            if (act == 1) {
                v0 = 1.0f / (1.0f + __expf(-v0)); v1 = 1.0f / (1.0f + __expf(-v1));
                v2 = 1.0f / (1.0f + __expf(-v2)); v3 = 1.0f / (1.0f + __expf(-v3));
            } else if (act == 2) {
                v0 = __expf(v0); v1 = __expf(v1); v2 = __expf(v2); v3 = __expf(v3);
            }
            *(float2*)&out[(size_t)row * CCH + col]       = make_float2(v0, v1);
            *(float2*)&out[(size_t)(row + 8) * CCH + col] = make_float2(v2, v3);
        }
}

// ---------- chunked scan ----------
__global__ void scan_p1(const float* __restrict__ td){
    int bj = blockIdx.x, c = threadIdx.x;
    float dec = __expf(td[c]);
    size_t base = ((size_t)(bj >> 5) * TT + (size_t)(bj & 31) * CHUNK_L) * CCH + c;
    float a = 0.0f;
    #pragma unroll 4
    for (int t = 0; t < CHUNK_L; t++)
        a = a * dec + g_k[base + (size_t)t * CCH] * g_v[base + (size_t)t * CCH];
    g_carry[(size_t)bj * CCH + c] = a;
}
__global__ void scan_p2(const float* __restrict__ td, const float* __restrict__ st){
    int b = blockIdx.x, c = threadIdx.x;
    float dL = __expf((float)CHUNK_L * td[c]);
    float s = st[b * CCH + c];
    for (int j = 0; j < NCHUNK; j++) {
        size_t o = (size_t)(b * NCHUNK + j) * CCH + c;
        g_sin[o] = s;
        s = s * dL + g_carry[o];
    }
}
__global__ void scan_p3(const float* __restrict__ td){
    int bj = blockIdx.x, c = threadIdx.x;
    float dec = __expf(td[c]);
    size_t base = ((size_t)(bj >> 5) * TT + (size_t)(bj & 31) * CHUNK_L) * CCH + c;
    float s = g_sin[(size_t)bj * CCH + c];
    #pragma unroll 4
    for (int t = 0; t < CHUNK_L; t++) {
        size_t i = base + (size_t)t * CCH;
        s = s * dec + g_k[i] * g_v[i];
        float o = g_r[i] * s;
        __nv_bfloat16 h, l; split2(o, h, l);
        g_oh[i] = h; g_ol[i] = l;
    }
}
__global__ void state_k(const float* __restrict__ x, float* __restrict__ dst){
    int i = blockIdx.x * 256 + threadIdx.x;
    if (i < BB * CCH)
        dst[i] = x[((size_t)(i >> 10) * TT + (TT - 1)) * CCH + (i & (CCH - 1))];
}

// ---------- host ----------
#define SYMADDR(var, p) do { void* _t; cudaGetSymbolAddress(&_t, var); p = _t; } while(0)

extern "C" void kernel_launch(void* const* d_in, const int* in_sizes, int n_in,
                              void* d_out, int out_size) {
    const float* x   = (const float*)d_in[0];
    const float* st  = (const float*)d_in[1];
    const float* Wr  = (const float*)d_in[2];
    const float* Wk  = (const float*)d_in[3];
    const float* Wv  = (const float*)d_in[4];
    const float* Wo  = (const float*)d_in[5];
    const float* tmr = (const float*)d_in[6];
    const float* tmk = (const float*)d_in[7];
    const float* tmv = (const float*)d_in[8];
    const float* td  = (const float*)d_in[9];
    float* dout = (float*)d_out;

    void *rin_h, *rin_l, *kin_h, *kin_l, *vin_h, *vin_l;
    void *pr, *pk, *pv, *oh, *ol;
    void *wrh, *wrl, *wkh, *wkl, *wvh, *wvl, *woh, *wol;
    SYMADDR(g_rin_h, rin_h); SYMADDR(g_rin_l, rin_l);
    SYMADDR(g_kin_h, kin_h); SYMADDR(g_kin_l, kin_l);
    SYMADDR(g_vin_h, vin_h); SYMADDR(g_vin_l, vin_l);
    SYMADDR(g_r, pr); SYMADDR(g_k, pk); SYMADDR(g_v, pv);
    SYMADDR(g_oh, oh); SYMADDR(g_ol, ol);
    SYMADDR(g_Wr_h, wrh); SYMADDR(g_Wr_l, wrl);
    SYMADDR(g_Wk_h, wkh); SYMADDR(g_Wk_l, wkl);
    SYMADDR(g_Wv_h, wvh); SYMADDR(g_Wv_l, wvl);
    SYMADDR(g_Wo_h, woh); SYMADDR(g_Wo_l, wol);

    cudaFuncSetAttribute(gemm_split, cudaFuncAttributeMaxDynamicSharedMemorySize, GEMM_SMEM);

    prep_k<<<NELEM / 256, 256>>>(x, st, tmr, tmk, tmv);
    split_w_k<<<CCH * CCH / 256, 256>>>(Wr, (__nv_bfloat16*)wrh, (__nv_bfloat16*)wrl);
    split_w_k<<<CCH * CCH / 256, 256>>>(Wk, (__nv_bfloat16*)wkh, (__nv_bfloat16*)wkl);
    split_w_k<<<CCH * CCH / 256, 256>>>(Wv, (__nv_bfloat16*)wvh, (__nv_bfloat16*)wvl);
    split_w_k<<<CCH * CCH / 256, 256>>>(Wo, (__nv_bfloat16*)woh, (__nv_bfloat16*)wol);

    dim3 gg(CCH / 128, MTOT / 128);   // (8, 128)
    gemm_split<<<gg, 256, GEMM_SMEM>>>(
        (const __nv_bfloat16*)rin_h, (const __nv_bfloat16*)rin_l,
        (const __nv_bfloat16*)wrh, (const __nv_bfloat16*)wrl, (float*)pr, 1);
    gemm_split<<<gg, 256, GEMM_SMEM>>>(
        (const __nv_bfloat16*)kin_h, (const __nv_bfloat16*)kin_l,
        (const __nv_bfloat16*)wkh, (const __nv_bfloat16*)wkl, (float*)pk, 2);
    gemm_split<<<gg, 256, GEMM_SMEM>>>(
        (const __nv_bfloat16*)vin_h, (const __nv_bfloat16*)vin_l,
        (const __nv_bfloat16*)wvh, (const __nv_bfloat16*)wvl, (float*)pv, 0);

    scan_p1<<<BB * NCHUNK, CCH>>>(td);
    scan_p2<<<BB, CCH>>>(td, st);
    scan_p3<<<BB * NCHUNK, CCH>>>(td);

    gemm_split<<<gg, 256, GEMM_SMEM>>>(
        (const __nv_bfloat16*)oh, (const __nv_bfloat16*)ol,
        (const __nv_bfloat16*)woh, (const __nv_bfloat16*)wol, dout, 0);

    if (out_size >= NELEM + BB * CCH)
        state_k<<<(BB * CCH + 255) / 256, 256>>>(x, dout + NELEM);
}

// round 8
// speedup vs baseline: 1.1700x; 1.1700x over previous
#include <cuda_runtime.h>
#include <cuda_bf16.h>
#include <cstdint>

#define BB 4
#define TT 4096
#define CCH 1024
#define MTOT (BB*TT)
#define NELEM (MTOT*CCH)
#define NCHUNK 64
#define CHUNK_L (TT/NCHUNK)

// GEMM tiling: CTA 256x128, KT=64, 256 threads = 8 warps (4M x 2N), warp 64x64
#define KT 64
#define ROWB 144                    // bytes per smem row (64 bf16 + 8 pad)
#define A_BYTES (256*ROWB)          // 36864
#define B_BYTES (128*ROWB)          // 18432
#define OFF_AH 0
#define OFF_AL A_BYTES
#define OFF_BH (2*A_BYTES)
#define OFF_BL (2*A_BYTES + B_BYTES)
#define STAGE_BYTES (2*A_BYTES + 2*B_BYTES)   // 110592
#define GEMM_SMEM (2*STAGE_BYTES)             // 221184

// ---------- scratch ----------
__device__ __nv_bfloat16 g_rin_h[NELEM], g_rin_l[NELEM];
__device__ __nv_bfloat16 g_kin_h[NELEM], g_kin_l[NELEM];
__device__ __nv_bfloat16 g_vin_h[NELEM], g_vin_l[NELEM];
__device__ float g_r[NELEM], g_k[NELEM], g_v[NELEM];
__device__ __nv_bfloat16 g_oh[NELEM], g_ol[NELEM];
__device__ __nv_bfloat16 g_Wr_h[CCH*CCH], g_Wr_l[CCH*CCH];
__device__ __nv_bfloat16 g_Wk_h[CCH*CCH], g_Wk_l[CCH*CCH];
__device__ __nv_bfloat16 g_Wv_h[CCH*CCH], g_Wv_l[CCH*CCH];
__device__ __nv_bfloat16 g_Wo_h[CCH*CCH], g_Wo_l[CCH*CCH];
__device__ float g_carry[BB*NCHUNK*CCH];
__device__ float g_sin[BB*NCHUNK*CCH];

// ---------- helpers ----------
static __device__ __forceinline__ uint32_t smem_u32(const void* p){
    uint32_t a;
    asm("{ .reg .u64 t; cvta.to.shared.u64 t, %1; cvt.u32.u64 %0, t; }" : "=r"(a) : "l"(p));
    return a;
}
static __device__ __forceinline__ void cp16(uint32_t s, const void* g){
    asm volatile("cp.async.cg.shared.global [%0], [%1], 16;" :: "r"(s), "l"(g) : "memory");
}
#define CP_COMMIT() asm volatile("cp.async.commit_group;" ::: "memory")
#define CP_WAIT(n)  asm volatile("cp.async.wait_group %0;" :: "n"(n) : "memory")

#define LDSM4(r0,r1,r2,r3,a) \
    asm volatile("ldmatrix.sync.aligned.m8n8.x4.shared.b16 {%0,%1,%2,%3}, [%4];" \
        : "=r"(r0),"=r"(r1),"=r"(r2),"=r"(r3) : "r"(a))

#define MMA16816(c, a, b) \
    asm volatile("mma.sync.aligned.m16n8k16.row.col.f32.bf16.bf16.f32 " \
        "{%0,%1,%2,%3}, {%4,%5,%6,%7}, {%8,%9}, {%0,%1,%2,%3};" \
        : "+f"((c)[0]),"+f"((c)[1]),"+f"((c)[2]),"+f"((c)[3]) \
        : "r"((a)[0]),"r"((a)[1]),"r"((a)[2]),"r"((a)[3]), "r"((b)[0]),"r"((b)[1]))

static __device__ __forceinline__ void split2(float v, __nv_bfloat16& h, __nv_bfloat16& l){
    h = __float2bfloat16(v);
    l = __float2bfloat16(v - __bfloat162float(h));
}

// ---------- prep ----------
__global__ void split_w_k(const float* __restrict__ w, __nv_bfloat16* __restrict__ h,
                          __nv_bfloat16* __restrict__ l){
    int i = blockIdx.x * 256 + threadIdx.x;
    __nv_bfloat16 a, b; split2(w[i], a, b); h[i] = a; l[i] = b;
}
__global__ void prep_k(const float* __restrict__ x, const float* __restrict__ st,
                       const float* __restrict__ tmr, const float* __restrict__ tmk,
                       const float* __restrict__ tmv){
    int i = blockIdx.x * 256 + threadIdx.x;
    int c = i & (CCH - 1);
    int bt = i >> 10;
    int t = bt & (TT - 1);
    float xv = x[i];
    float xm = (t == 0) ? st[(bt >> 12) * CCH + c] : x[i - CCH];
    float mr = tmr[c], mk = tmk[c], mv = tmv[c];
    __nv_bfloat16 h, l;
    split2(xv * mr + xm * (1.0f - mr), h, l); g_rin_h[i] = h; g_rin_l[i] = l;
    split2(xv * mk + xm * (1.0f - mk), h, l); g_kin_h[i] = h; g_kin_l[i] = l;
    split2(xv * mv + xm * (1.0f - mv), h, l); g_vin_h[i] = h; g_vin_l[i] = l;
}

// ---------- GEMM: out[m,n] = sum_c A[m,c]*W[n,c], split-bf16 (3 products) ----------
struct GemmBatch {
    const __nv_bfloat16 *ah[3], *al[3], *bh[3], *bl[3];
    float* out[3];
    int act[3];
};

static __device__ __forceinline__ void fill_stage(uint32_t st,
        const __nv_bfloat16* __restrict__ Ah, const __nv_bfloat16* __restrict__ Al,
        const __nv_bfloat16* __restrict__ Bh, const __nv_bfloat16* __restrict__ Bl,
        int m0, int n0, int k0, int tid){
    #pragma unroll
    for (int i = 0; i < 8; i++) {           // A: 256 rows x 8 chunks
        int idx = tid + i * 256;
        int r = idx >> 3, ch = idx & 7;
        uint32_t d = (uint32_t)(r * ROWB + ch * 16);
        size_t s = (size_t)(m0 + r) * CCH + k0 + ch * 8;
        cp16(st + OFF_AH + d, Ah + s);
        cp16(st + OFF_AL + d, Al + s);
    }
    #pragma unroll
    for (int i = 0; i < 4; i++) {           // B: 128 rows x 8 chunks
        int idx = tid + i * 256;
        int r = idx >> 3, ch = idx & 7;
        uint32_t d = (uint32_t)(r * ROWB + ch * 16);
        size_t s = (size_t)(n0 + r) * CCH + k0 + ch * 8;
        cp16(st + OFF_BH + d, Bh + s);
        cp16(st + OFF_BL + d, Bl + s);
    }
}

__global__ void __launch_bounds__(256, 1)
gemm_split(GemmBatch p){
    extern __shared__ __align__(16) char smem[];
    uint32_t sb = smem_u32(smem);
    const int z = blockIdx.z;
    const __nv_bfloat16* __restrict__ Ah = p.ah[z];
    const __nv_bfloat16* __restrict__ Al = p.al[z];
    const __nv_bfloat16* __restrict__ Bh = p.bh[z];
    const __nv_bfloat16* __restrict__ Bl = p.bl[z];
    float* __restrict__ out = p.out[z];
    const int act = p.act[z];

    const int tid = threadIdx.x, lane = tid & 31, wid = tid >> 5;
    const int wm = wid >> 1, wn = wid & 1;        // 4 x 2 warp grid, warp 64x64
    const int m0 = blockIdx.y * 256, n0 = blockIdx.x * 128;

    float acc[4][8][4];
    #pragma unroll
    for (int i = 0; i < 4; i++)
        #pragma unroll
        for (int j = 0; j < 8; j++)
            #pragma unroll
            for (int q = 0; q < 4; q++) acc[i][j][q] = 0.0f;

    fill_stage(sb,               Ah, Al, Bh, Bl, m0, n0, 0,  tid); CP_COMMIT();
    fill_stage(sb + STAGE_BYTES, Ah, Al, Bh, Bl, m0, n0, KT, tid); CP_COMMIT();

    // precomputed fragment base offsets (byte offsets within stage)
    const uint32_t a_base = (uint32_t)((wm * 64 + ((lane >> 3) & 1) * 8 + (lane & 7)) * ROWB
                                       + (lane >> 4) * 16);
    const uint32_t b_base = (uint32_t)((wn * 64 + ((lane >> 4) & 1) * 8 + (lane & 7)) * ROWB
                                       + ((lane >> 3) & 1) * 16);

    const int NITER = CCH / KT;   // 16
    for (int ks = 0; ks < NITER; ks++) {
        uint32_t st = sb + (uint32_t)(ks & 1) * STAGE_BYTES;
        if (ks + 1 < NITER) CP_WAIT(1); else CP_WAIT(0);
        __syncthreads();

        for (int kk = 0; kk < KT; kk += 16) {
            uint32_t ah[4][4], al[4][4], bh[8][2], bl[8][2];
            #pragma unroll
            for (int mt = 0; mt < 4; mt++) {
                uint32_t a = st + a_base + (uint32_t)(mt * 16 * ROWB + kk * 2);
                LDSM4(ah[mt][0], ah[mt][1], ah[mt][2], ah[mt][3], a + OFF_AH);
                LDSM4(al[mt][0], al[mt][1], al[mt][2], al[mt][3], a + OFF_AL);
            }
            #pragma unroll
            for (int pnt = 0; pnt < 4; pnt++) {
                uint32_t b = st + b_base + (uint32_t)(pnt * 16 * ROWB + kk * 2);
                LDSM4(bh[2*pnt][0], bh[2*pnt][1], bh[2*pnt+1][0], bh[2*pnt+1][1], b + OFF_BH);
                LDSM4(bl[2*pnt][0], bl[2*pnt][1], bl[2*pnt+1][0], bl[2*pnt+1][1], b + OFF_BL);
            }
            #pragma unroll
            for (int mt = 0; mt < 4; mt++)
                #pragma unroll
                for (int nt = 0; nt < 8; nt++) {
                    MMA16816(acc[mt][nt], ah[mt], bh[nt]);
                    MMA16816(acc[mt][nt], ah[mt], bl[nt]);
                    MMA16816(acc[mt][nt], al[mt], bh[nt]);
                }
        }
        __syncthreads();
        if (ks + 2 < NITER) {
            fill_stage(st, Ah, Al, Bh, Bl, m0, n0, (ks + 2) * KT, tid);
            CP_COMMIT();
        }
    }

    // epilogue with fused activation
    #pragma unroll
    for (int mt = 0; mt < 4; mt++)
        #pragma unroll
        for (int nt = 0; nt < 8; nt++) {
            int row = m0 + wm * 64 + mt * 16 + (lane >> 2);
            int col = n0 + wn * 64 + nt * 8 + (lane & 3) * 2;
            float v0 = acc[mt][nt][0], v1 = acc[mt][nt][1];
            float v2 = acc[mt][nt][2], v3 = acc[mt][nt][3];
            if (act == 1) {
                v0 = 1.0f / (1.0f + __expf(-v0)); v1 = 1.0f / (1.0f + __expf(-v1));
                v2 = 1.0f / (1.0f + __expf(-v2)); v3 = 1.0f / (1.0f + __expf(-v3));
            } else if (act == 2) {
                v0 = __expf(v0); v1 = __expf(v1); v2 = __expf(v2); v3 = __expf(v3);
            }
            *(float2*)&out[(size_t)row * CCH + col]       = make_float2(v0, v1);
            *(float2*)&out[(size_t)(row + 8) * CCH + col] = make_float2(v2, v3);
        }
}

// ---------- chunked scan ----------
__global__ void scan_p1(const float* __restrict__ td){
    int bj = blockIdx.x, c = threadIdx.x;
    float dec = __expf(td[c]);
    size_t base = ((size_t)(bj / NCHUNK) * TT + (size_t)(bj % NCHUNK) * CHUNK_L) * CCH + c;
    float a = 0.0f;
    #pragma unroll 4
    for (int t = 0; t < CHUNK_L; t++)
        a = a * dec + g_k[base + (size_t)t * CCH] * g_v[base + (size_t)t * CCH];
    g_carry[(size_t)bj * CCH + c] = a;
}
__global__ void scan_p2(const float* __restrict__ td, const float* __restrict__ st){
    int b = blockIdx.x, c = threadIdx.x;
    float dL = __expf((float)CHUNK_L * td[c]);
    float s = st[b * CCH + c];
    for (int j = 0; j < NCHUNK; j++) {
        size_t o = (size_t)(b * NCHUNK + j) * CCH + c;
        g_sin[o] = s;
        s = s * dL + g_carry[o];
    }
}
__global__ void scan_p3(const float* __restrict__ td){
    int bj = blockIdx.x, c = threadIdx.x;
    float dec = __expf(td[c]);
    size_t base = ((size_t)(bj / NCHUNK) * TT + (size_t)(bj % NCHUNK) * CHUNK_L) * CCH + c;
    float s = g_sin[(size_t)bj * CCH + c];
    #pragma unroll 4
    for (int t = 0; t < CHUNK_L; t++) {
        size_t i = base + (size_t)t * CCH;
        s = s * dec + g_k[i] * g_v[i];
        float o = g_r[i] * s;
        __nv_bfloat16 h, l; split2(o, h, l);
        g_oh[i] = h; g_ol[i] = l;
    }
}
__global__ void state_k(const float* __restrict__ x, float* __restrict__ dst){
    int i = blockIdx.x * 256 + threadIdx.x;
    if (i < BB * CCH)
        dst[i] = x[((size_t)(i >> 10) * TT + (TT - 1)) * CCH + (i & (CCH - 1))];
}

// ---------- host ----------
#define SYMADDR(var, p) do { void* _t; cudaGetSymbolAddress(&_t, var); p = _t; } while(0)

extern "C" void kernel_launch(void* const* d_in, const int* in_sizes, int n_in,
                              void* d_out, int out_size) {
    const float* x   = (const float*)d_in[0];
    const float* st  = (const float*)d_in[1];
    const float* Wr  = (const float*)d_in[2];
    const float* Wk  = (const float*)d_in[3];
    const float* Wv  = (const float*)d_in[4];
    const float* Wo  = (const float*)d_in[5];
    const float* tmr = (const float*)d_in[6];
    const float* tmk = (const float*)d_in[7];
    const float* tmv = (const float*)d_in[8];
    const float* td  = (const float*)d_in[9];
    float* dout = (float*)d_out;

    void *rin_h, *rin_l, *kin_h, *kin_l, *vin_h, *vin_l;
    void *pr, *pk, *pv, *oh, *ol;
    void *wrh, *wrl, *wkh, *wkl, *wvh, *wvl, *woh, *wol;
    SYMADDR(g_rin_h, rin_h); SYMADDR(g_rin_l, rin_l);
    SYMADDR(g_kin_h, kin_h); SYMADDR(g_kin_l, kin_l);
    SYMADDR(g_vin_h, vin_h); SYMADDR(g_vin_l, vin_l);
    SYMADDR(g_r, pr); SYMADDR(g_k, pk); SYMADDR(g_v, pv);
    SYMADDR(g_oh, oh); SYMADDR(g_ol, ol);
    SYMADDR(g_Wr_h, wrh); SYMADDR(g_Wr_l, wrl);
    SYMADDR(g_Wk_h, wkh); SYMADDR(g_Wk_l, wkl);
    SYMADDR(g_Wv_h, wvh); SYMADDR(g_Wv_l, wvl);
    SYMADDR(g_Wo_h, woh); SYMADDR(g_Wo_l, wol);

    cudaFuncSetAttribute(gemm_split, cudaFuncAttributeMaxDynamicSharedMemorySize, GEMM_SMEM);

    prep_k<<<NELEM / 256, 256>>>(x, st, tmr, tmk, tmv);
    split_w_k<<<CCH * CCH / 256, 256>>>(Wr, (__nv_bfloat16*)wrh, (__nv_bfloat16*)wrl);
    split_w_k<<<CCH * CCH / 256, 256>>>(Wk, (__nv_bfloat16*)wkh, (__nv_bfloat16*)wkl);
    split_w_k<<<CCH * CCH / 256, 256>>>(Wv, (__nv_bfloat16*)wvh, (__nv_bfloat16*)wvl);
    split_w_k<<<CCH * CCH / 256, 256>>>(Wo, (__nv_bfloat16*)woh, (__nv_bfloat16*)wol);

    // merged r/k/v GEMMs: grid z picks operand set
    GemmBatch gb;
    gb.ah[0] = (const __nv_bfloat16*)rin_h; gb.al[0] = (const __nv_bfloat16*)rin_l;
    gb.bh[0] = (const __nv_bfloat16*)wrh;   gb.bl[0] = (const __nv_bfloat16*)wrl;
    gb.out[0] = (float*)pr; gb.act[0] = 1;
    gb.ah[1] = (const __nv_bfloat16*)kin_h; gb.al[1] = (const __nv_bfloat16*)kin_l;
    gb.bh[1] = (const __nv_bfloat16*)wkh;   gb.bl[1] = (const __nv_bfloat16*)wkl;
    gb.out[1] = (float*)pk; gb.act[1] = 2;
    gb.ah[2] = (const __nv_bfloat16*)vin_h; gb.al[2] = (const __nv_bfloat16*)vin_l;
    gb.bh[2] = (const __nv_bfloat16*)wvh;   gb.bl[2] = (const __nv_bfloat16*)wvl;
    gb.out[2] = (float*)pv; gb.act[2] = 0;

    dim3 gg(CCH / 128, MTOT / 256, 3);   // (8, 64, 3)
    gemm_split<<<gg, 256, GEMM_SMEM>>>(gb);

    scan_p1<<<BB * NCHUNK, CCH>>>(td);
    scan_p2<<<BB, CCH>>>(td, st);
    scan_p3<<<BB * NCHUNK, CCH>>>(td);

    GemmBatch go;
    go.ah[0] = (const __nv_bfloat16*)oh; go.al[0] = (const __nv_bfloat16*)ol;
    go.bh[0] = (const __nv_bfloat16*)woh; go.bl[0] = (const __nv_bfloat16*)wol;
    go.out[0] = dout; go.act[0] = 0;
    go.ah[1] = go.ah[0]; go.al[1] = go.al[0]; go.bh[1] = go.bh[0]; go.bl[1] = go.bl[0];
    go.out[1] = dout; go.act[1] = 0;
    go.ah[2] = go.ah[0]; go.al[2] = go.al[0]; go.bh[2] = go.bh[0]; go.bl[2] = go.bl[0];
    go.out[2] = dout; go.act[2] = 0;

    dim3 g1(CCH / 128, MTOT / 256, 1);
    gemm_split<<<g1, 256, GEMM_SMEM>>>(go);

    if (out_size >= NELEM + BB * CCH)
        state_k<<<(BB * CCH + 255) / 256, 256>>>(x, dout + NELEM);
}

// round 9
// speedup vs baseline: 1.6012x; 1.3685x over previous
#include <cuda_runtime.h>
#include <cuda_fp16.h>
#include <cstdint>

#define BB 4
#define TT 4096
#define CCH 1024
#define MTOT (BB*TT)
#define NELEM (MTOT*CCH)
#define NCHUNK 64
#define CHUNK_L (TT/NCHUNK)

// GEMM: CTA 256x128, KT=64, 256 thr = 8 warps (4M x 2N), warp 64x64
// A: single fp16 limb. B: two fp16 limbs. 2 MMA products per (mt,nt).
#define KT 64
#define ROWB 144                    // 64 fp16 (128B) + 16B pad
#define A_BYTES (256*ROWB)          // 36864
#define B_BYTES (128*ROWB)          // 18432
#define OFF_A  0
#define OFF_BH A_BYTES
#define OFF_BL (A_BYTES + B_BYTES)
#define STAGE_BYTES (A_BYTES + 2*B_BYTES)     // 73728
#define NSTAGE 3
#define GEMM_SMEM (NSTAGE*STAGE_BYTES)        // 221184

// ---------- scratch ----------
__device__ __half g_rin[NELEM], g_kin[NELEM], g_vin[NELEM];
__device__ float g_r[NELEM], g_k[NELEM], g_v[NELEM];
__device__ __half g_of[NELEM];
__device__ __half g_Wr_h[CCH*CCH], g_Wr_l[CCH*CCH];
__device__ __half g_Wk_h[CCH*CCH], g_Wk_l[CCH*CCH];
__device__ __half g_Wv_h[CCH*CCH], g_Wv_l[CCH*CCH];
__device__ __half g_Wo_h[CCH*CCH], g_Wo_l[CCH*CCH];
__device__ float g_carry[BB*NCHUNK*CCH];
__device__ float g_sin[BB*NCHUNK*CCH];

// ---------- helpers ----------
static __device__ __forceinline__ uint32_t smem_u32(const void* p){
    uint32_t a;
    asm("{ .reg .u64 t; cvta.to.shared.u64 t, %1; cvt.u32.u64 %0, t; }" : "=r"(a) : "l"(p));
    return a;
}
static __device__ __forceinline__ void cp16(uint32_t s, const void* g){
    asm volatile("cp.async.cg.shared.global [%0], [%1], 16;" :: "r"(s), "l"(g) : "memory");
}
#define CP_COMMIT() asm volatile("cp.async.commit_group;" ::: "memory")
#define CP_WAIT(n)  asm volatile("cp.async.wait_group %0;" :: "n"(n) : "memory")

#define LDSM4(r0,r1,r2,r3,a) \
    asm volatile("ldmatrix.sync.aligned.m8n8.x4.shared.b16 {%0,%1,%2,%3}, [%4];" \
        : "=r"(r0),"=r"(r1),"=r"(r2),"=r"(r3) : "r"(a))

#define MMAF16(c, a, b) \
    asm volatile("mma.sync.aligned.m16n8k16.row.col.f32.f16.f16.f32 " \
        "{%0,%1,%2,%3}, {%4,%5,%6,%7}, {%8,%9}, {%0,%1,%2,%3};" \
        : "+f"((c)[0]),"+f"((c)[1]),"+f"((c)[2]),"+f"((c)[3]) \
        : "r"((a)[0]),"r"((a)[1]),"r"((a)[2]),"r"((a)[3]), "r"((b)[0]),"r"((b)[1]))

static __device__ __forceinline__ void splith(float v, __half& h, __half& l){
    h = __float2half_rn(v);
    l = __float2half_rn(v - __half2float(h));
}

// ---------- prep ----------
__global__ void split_w_k(const float* __restrict__ w, __half* __restrict__ h,
                          __half* __restrict__ l){
    int i = blockIdx.x * 256 + threadIdx.x;
    __half a, b; splith(w[i], a, b); h[i] = a; l[i] = b;
}
__global__ void prep_k(const float* __restrict__ x, const float* __restrict__ st,
                       const float* __restrict__ tmr, const float* __restrict__ tmk,
                       const float* __restrict__ tmv){
    int i = blockIdx.x * 256 + threadIdx.x;
    int c = i & (CCH - 1);
    int bt = i >> 10;
    int t = bt & (TT - 1);
    float xv = x[i];
    float xm = (t == 0) ? st[(bt >> 12) * CCH + c] : x[i - CCH];
    float mr = tmr[c], mk = tmk[c], mv = tmv[c];
    g_rin[i] = __float2half_rn(xv * mr + xm * (1.0f - mr));
    g_kin[i] = __float2half_rn(xv * mk + xm * (1.0f - mk));
    g_vin[i] = __float2half_rn(xv * mv + xm * (1.0f - mv));
}

// ---------- GEMM: out[m,n] = sum_c A[m,c]*W[n,c] ----------
struct GemmBatch {
    const __half *a[3], *bh[3], *bl[3];
    float* out[3];
    int act[3];
};

static __device__ __forceinline__ void fill_stage(uint32_t st,
        const __half* __restrict__ A, const __half* __restrict__ Bh,
        const __half* __restrict__ Bl, int m0, int n0, int k0, int tid){
    #pragma unroll
    for (int i = 0; i < 8; i++) {           // A: 256 rows x 8 chunks of 8 fp16
        int idx = tid + i * 256;
        int r = idx >> 3, ch = idx & 7;
        cp16(st + OFF_A + (uint32_t)(r * ROWB + ch * 16),
             A + (size_t)(m0 + r) * CCH + k0 + ch * 8);
    }
    #pragma unroll
    for (int i = 0; i < 4; i++) {           // B: 128 rows x 8 chunks, 2 limbs
        int idx = tid + i * 256;
        int r = idx >> 3, ch = idx & 7;
        uint32_t d = (uint32_t)(r * ROWB + ch * 16);
        size_t s = (size_t)(n0 + r) * CCH + k0 + ch * 8;
        cp16(st + OFF_BH + d, Bh + s);
        cp16(st + OFF_BL + d, Bl + s);
    }
}

__global__ void __launch_bounds__(256, 1)
gemm_split(GemmBatch p){
    extern __shared__ __align__(16) char smem[];
    uint32_t sb = smem_u32(smem);
    const int z = blockIdx.z;
    const __half* __restrict__ A  = p.a[z];
    const __half* __restrict__ Bh = p.bh[z];
    const __half* __restrict__ Bl = p.bl[z];
    float* __restrict__ out = p.out[z];
    const int act = p.act[z];

    const int tid = threadIdx.x, lane = tid & 31, wid = tid >> 5;
    const int wm = wid >> 1, wn = wid & 1;        // 4 x 2 warp grid, warp 64x64
    const int m0 = blockIdx.y * 256, n0 = blockIdx.x * 128;

    float acc[4][8][4];
    #pragma unroll
    for (int i = 0; i < 4; i++)
        #pragma unroll
        for (int j = 0; j < 8; j++)
            #pragma unroll
            for (int q = 0; q < 4; q++) acc[i][j][q] = 0.0f;

    #pragma unroll
    for (int s = 0; s < NSTAGE; s++) {
        fill_stage(sb + (uint32_t)s * STAGE_BYTES, A, Bh, Bl, m0, n0, s * KT, tid);
        CP_COMMIT();
    }

    const uint32_t a_base = (uint32_t)((wm * 64 + ((lane >> 3) & 1) * 8 + (lane & 7)) * ROWB
                                       + (lane >> 4) * 16);
    const uint32_t b_base = (uint32_t)((wn * 64 + ((lane >> 4) & 1) * 8 + (lane & 7)) * ROWB
                                       + ((lane >> 3) & 1) * 16);

    const int NITER = CCH / KT;   // 16
    for (int ks = 0; ks < NITER; ks++) {
        uint32_t st = sb + (uint32_t)(ks % NSTAGE) * STAGE_BYTES;
        if (ks < NITER - 2)      CP_WAIT(2);
        else if (ks == NITER-2)  CP_WAIT(1);
        else                     CP_WAIT(0);
        __syncthreads();

        #pragma unroll
        for (int kk = 0; kk < KT; kk += 16) {
            uint32_t ah[4][4], bh[8][2], bl[8][2];
            #pragma unroll
            for (int mt = 0; mt < 4; mt++) {
                uint32_t a = st + OFF_A + a_base + (uint32_t)(mt * 16 * ROWB + kk * 2);
                LDSM4(ah[mt][0], ah[mt][1], ah[mt][2], ah[mt][3], a);
            }
            #pragma unroll
            for (int pnt = 0; pnt < 4; pnt++) {
                uint32_t b = st + b_base + (uint32_t)(pnt * 16 * ROWB + kk * 2);
                LDSM4(bh[2*pnt][0], bh[2*pnt][1], bh[2*pnt+1][0], bh[2*pnt+1][1], b + OFF_BH);
                LDSM4(bl[2*pnt][0], bl[2*pnt][1], bl[2*pnt+1][0], bl[2*pnt+1][1], b + OFF_BL);
            }
            #pragma unroll
            for (int mt = 0; mt < 4; mt++)
                #pragma unroll
                for (int nt = 0; nt < 8; nt++) {
                    MMAF16(acc[mt][nt], ah[mt], bh[nt]);
                    MMAF16(acc[mt][nt], ah[mt], bl[nt]);
                }
        }
        __syncthreads();
        if (ks + NSTAGE < NITER) {
            fill_stage(st, A, Bh, Bl, m0, n0, (ks + NSTAGE) * KT, tid);
            CP_COMMIT();
        }
    }

    // epilogue with fused activation
    #pragma unroll
    for (int mt = 0; mt < 4; mt++)
        #pragma unroll
        for (int nt = 0; nt < 8; nt++) {
            int row = m0 + wm * 64 + mt * 16 + (lane >> 2);
            int col = n0 + wn * 64 + nt * 8 + (lane & 3) * 2;
            float v0 = acc[mt][nt][0], v1 = acc[mt][nt][1];
            float v2 = acc[mt][nt][2], v3 = acc[mt][nt][3];
            if (act == 1) {
                v0 = 1.0f / (1.0f + __expf(-v0)); v1 = 1.0f / (1.0f + __expf(-v1));
                v2 = 1.0f / (1.0f + __expf(-v2)); v3 = 1.0f / (1.0f + __expf(-v3));
            } else if (act == 2) {
                v0 = __expf(v0); v1 = __expf(v1); v2 = __expf(v2); v3 = __expf(v3);
            }
            *(float2*)&out[(size_t)row * CCH + col]       = make_float2(v0, v1);
            *(float2*)&out[(size_t)(row + 8) * CCH + col] = make_float2(v2, v3);
        }
}

// ---------- chunked scan ----------
__global__ void scan_p1(const float* __restrict__ td){
    int bj = blockIdx.x, c = threadIdx.x;
    float dec = __expf(td[c]);
    size_t base = ((size_t)(bj / NCHUNK) * TT + (size_t)(bj % NCHUNK) * CHUNK_L) * CCH + c;
    float a = 0.0f;
    #pragma unroll 4
    for (int t = 0; t < CHUNK_L; t++)
        a = a * dec + g_k[base + (size_t)t * CCH] * g_v[base + (size_t)t * CCH];
    g_carry[(size_t)bj * CCH + c] = a;
}
__global__ void scan_p2(const float* __restrict__ td, const float* __restrict__ st){
    int b = blockIdx.x, c = threadIdx.x;
    float dL = __expf((float)CHUNK_L * td[c]);
    float s = st[b * CCH + c];
    for (int j = 0; j < NCHUNK; j++) {
        size_t o = (size_t)(b * NCHUNK + j) * CCH + c;
        g_sin[o] = s;
        s = s * dL + g_carry[o];
    }
}
__global__ void scan_p3(const float* __restrict__ td){
    int bj = blockIdx.x, c = threadIdx.x;
    float dec = __expf(td[c]);
    size_t base = ((size_t)(bj / NCHUNK) * TT + (size_t)(bj % NCHUNK) * CHUNK_L) * CCH + c;
    float s = g_sin[(size_t)bj * CCH + c];
    #pragma unroll 4
    for (int t = 0; t < CHUNK_L; t++) {
        size_t i = base + (size_t)t * CCH;
        s = s * dec + g_k[i] * g_v[i];
        g_of[i] = __float2half_rn(g_r[i] * s);
    }
}
__global__ void state_k(const float* __restrict__ x, float* __restrict__ dst){
    int i = blockIdx.x * 256 + threadIdx.x;
    if (i < BB * CCH)
        dst[i] = x[((size_t)(i >> 10) * TT + (TT - 1)) * CCH + (i & (CCH - 1))];
}

// ---------- host ----------
#define SYMADDR(var, p) do { void* _t; cudaGetSymbolAddress(&_t, var); p = _t; } while(0)

extern "C" void kernel_launch(void* const* d_in, const int* in_sizes, int n_in,
                              void* d_out, int out_size) {
    const float* x   = (const float*)d_in[0];
    const float* st  = (const float*)d_in[1];
    const float* Wr  = (const float*)d_in[2];
    const float* Wk  = (const float*)d_in[3];
    const float* Wv  = (const float*)d_in[4];
    const float* Wo  = (const float*)d_in[5];
    const float* tmr = (const float*)d_in[6];
    const float* tmk = (const float*)d_in[7];
    const float* tmv = (const float*)d_in[8];
    const float* td  = (const float*)d_in[9];
    float* dout = (float*)d_out;

    void *rin, *kin, *vin, *pr, *pk, *pv, *of;
    void *wrh, *wrl, *wkh, *wkl, *wvh, *wvl, *woh, *wol;
    SYMADDR(g_rin, rin); SYMADDR(g_kin, kin); SYMADDR(g_vin, vin);
    SYMADDR(g_r, pr); SYMADDR(g_k, pk); SYMADDR(g_v, pv);
    SYMADDR(g_of, of);
    SYMADDR(g_Wr_h, wrh); SYMADDR(g_Wr_l, wrl);
    SYMADDR(g_Wk_h, wkh); SYMADDR(g_Wk_l, wkl);
    SYMADDR(g_Wv_h, wvh); SYMADDR(g_Wv_l, wvl);
    SYMADDR(g_Wo_h, woh); SYMADDR(g_Wo_l, wol);

    cudaFuncSetAttribute(gemm_split, cudaFuncAttributeMaxDynamicSharedMemorySize, GEMM_SMEM);

    split_w_k<<<CCH * CCH / 256, 256>>>(Wr, (__half*)wrh, (__half*)wrl);
    split_w_k<<<CCH * CCH / 256, 256>>>(Wk, (__half*)wkh, (__half*)wkl);
    split_w_k<<<CCH * CCH / 256, 256>>>(Wv, (__half*)wvh, (__half*)wvl);
    split_w_k<<<CCH * CCH / 256, 256>>>(Wo, (__half*)woh, (__half*)wol);
    prep_k<<<NELEM / 256, 256>>>(x, st, tmr, tmk, tmv);

    GemmBatch gb;
    gb.a[0] = (const __half*)rin; gb.bh[0] = (const __half*)wrh; gb.bl[0] = (const __half*)wrl;
    gb.out[0] = (float*)pr; gb.act[0] = 1;
    gb.a[1] = (const __half*)kin; gb.bh[1] = (const __half*)wkh; gb.bl[1] = (const __half*)wkl;
    gb.out[1] = (float*)pk; gb.act[1] = 2;
    gb.a[2] = (const __half*)vin; gb.bh[2] = (const __half*)wvh; gb.bl[2] = (const __half*)wvl;
    gb.out[2] = (float*)pv; gb.act[2] = 0;

    dim3 gg(CCH / 128, MTOT / 256, 3);   // (8, 64, 3)
    gemm_split<<<gg, 256, GEMM_SMEM>>>(gb);

    scan_p1<<<BB * NCHUNK, CCH>>>(td);
    scan_p2<<<BB, CCH>>>(td, st);
    scan_p3<<<BB * NCHUNK, CCH>>>(td);

    GemmBatch go;
    go.a[0] = (const __half*)of; go.bh[0] = (const __half*)woh; go.bl[0] = (const __half*)wol;
    go.out[0] = dout; go.act[0] = 0;
    go.a[1] = go.a[0]; go.bh[1] = go.bh[0]; go.bl[1] = go.bl[0];
    go.out[1] = dout; go.act[1] = 0;
    go.a[2] = go.a[0]; go.bh[2] = go.bh[0]; go.bl[2] = go.bl[0];
    go.out[2] = dout; go.act[2] = 0;

    dim3 g1(CCH / 128, MTOT / 256, 1);
    gemm_split<<<g1, 256, GEMM_SMEM>>>(go);

    if (out_size >= NELEM + BB * CCH)
        state_k<<<(BB * CCH + 255) / 256, 256>>>(x, dout + NELEM);
}

// round 10
// speedup vs baseline: 2.3191x; 1.4484x over previous
#include <cuda_runtime.h>
#include <cuda_fp16.h>
#include <cstdint>

#define BB 4
#define TT 4096
#define CCH 1024
#define MTOT (BB*TT)
#define NELEM (MTOT*CCH)
#define NCHUNK 64
#define CHUNK_L (TT/NCHUNK)

// GEMM: CTA 256x128, KT=64, 256 thr = 8 warps (4M x 2N), warp 64x64
// A and B single fp16 -> 1 MMA per (mt,nt) per k16.
#define KT 64
#define ROWB 144                    // 64 fp16 (128B) + 16B pad
#define A_BYTES (256*ROWB)          // 36864
#define B_BYTES (128*ROWB)          // 18432
#define OFF_A  0
#define OFF_B  A_BYTES
#define STAGE_BYTES (A_BYTES + B_BYTES)       // 55296
#define NSTAGE 4
#define GEMM_SMEM (NSTAGE*STAGE_BYTES)        // 221184

// ---------- scratch ----------
__device__ __half g_rin[NELEM], g_kin[NELEM], g_vin[NELEM];
__device__ float g_r[NELEM], g_k[NELEM], g_v[NELEM];
__device__ __half g_of[NELEM];
__device__ __half g_Wr[CCH*CCH], g_Wk[CCH*CCH], g_Wv[CCH*CCH], g_Wo[CCH*CCH];
__device__ float g_carry[BB*NCHUNK*CCH];
__device__ float g_sin[BB*NCHUNK*CCH];

// ---------- helpers ----------
static __device__ __forceinline__ uint32_t smem_u32(const void* p){
    uint32_t a;
    asm("{ .reg .u64 t; cvta.to.shared.u64 t, %1; cvt.u32.u64 %0, t; }" : "=r"(a) : "l"(p));
    return a;
}
static __device__ __forceinline__ void cp16(uint32_t s, const void* g){
    asm volatile("cp.async.cg.shared.global [%0], [%1], 16;" :: "r"(s), "l"(g) : "memory");
}
#define CP_COMMIT() asm volatile("cp.async.commit_group;" ::: "memory")
#define CP_WAIT(n)  asm volatile("cp.async.wait_group %0;" :: "n"(n) : "memory")

#define LDSM4(r0,r1,r2,r3,a) \
    asm volatile("ldmatrix.sync.aligned.m8n8.x4.shared.b16 {%0,%1,%2,%3}, [%4];" \
        : "=r"(r0),"=r"(r1),"=r"(r2),"=r"(r3) : "r"(a))

#define MMAF16(c, a, b) \
    asm volatile("mma.sync.aligned.m16n8k16.row.col.f32.f16.f16.f32 " \
        "{%0,%1,%2,%3}, {%4,%5,%6,%7}, {%8,%9}, {%0,%1,%2,%3};" \
        : "+f"((c)[0]),"+f"((c)[1]),"+f"((c)[2]),"+f"((c)[3]) \
        : "r"((a)[0]),"r"((a)[1]),"r"((a)[2]),"r"((a)[3]), "r"((b)[0]),"r"((b)[1]))

// ---------- prep ----------
struct CvtBatch { const float* src[4]; __half* dst[4]; };
__global__ void cvt_w_k(CvtBatch p){
    int i = blockIdx.x * 256 + threadIdx.x;
    const float* s = p.src[blockIdx.y];
    __half* d = p.dst[blockIdx.y];
    float4 v = *(const float4*)&s[i * 4];
    __half2 h0 = __floats2half2_rn(v.x, v.y);
    __half2 h1 = __floats2half2_rn(v.z, v.w);
    *(__half2*)&d[i * 4]     = h0;
    *(__half2*)&d[i * 4 + 2] = h1;
}
__global__ void prep_k(const float* __restrict__ x, const float* __restrict__ st,
                       const float* __restrict__ tmr, const float* __restrict__ tmk,
                       const float* __restrict__ tmv){
    int i = blockIdx.x * 256 + threadIdx.x;
    int c = i & (CCH - 1);
    int bt = i >> 10;
    int t = bt & (TT - 1);
    float xv = x[i];
    float xm = (t == 0) ? st[(bt >> 12) * CCH + c] : x[i - CCH];
    float mr = tmr[c], mk = tmk[c], mv = tmv[c];
    g_rin[i] = __float2half_rn(xv * mr + xm * (1.0f - mr));
    g_kin[i] = __float2half_rn(xv * mk + xm * (1.0f - mk));
    g_vin[i] = __float2half_rn(xv * mv + xm * (1.0f - mv));
}

// ---------- GEMM: out[m,n] = sum_c A[m,c]*W[n,c] ----------
struct GemmBatch {
    const __half *a[3], *b[3];
    float* out[3];
    int act[3];
};

static __device__ __forceinline__ void fill_stage(uint32_t st,
        const __half* __restrict__ A, const __half* __restrict__ B,
        int m0, int n0, int k0, int tid){
    #pragma unroll
    for (int i = 0; i < 8; i++) {           // A: 256 rows x 8 chunks of 8 fp16
        int idx = tid + i * 256;
        int r = idx >> 3, ch = idx & 7;
        cp16(st + OFF_A + (uint32_t)(r * ROWB + ch * 16),
             A + (size_t)(m0 + r) * CCH + k0 + ch * 8);
    }
    #pragma unroll
    for (int i = 0; i < 4; i++) {           // B: 128 rows x 8 chunks
        int idx = tid + i * 256;
        int r = idx >> 3, ch = idx & 7;
        cp16(st + OFF_B + (uint32_t)(r * ROWB + ch * 16),
             B + (size_t)(n0 + r) * CCH + k0 + ch * 8);
    }
}

__global__ void __launch_bounds__(256, 1)
gemm_half(GemmBatch p){
    extern __shared__ __align__(16) char smem[];
    uint32_t sb = smem_u32(smem);
    const int z = blockIdx.z;
    const __half* __restrict__ A = p.a[z];
    const __half* __restrict__ B = p.b[z];
    float* __restrict__ out = p.out[z];
    const int act = p.act[z];

    const int tid = threadIdx.x, lane = tid & 31, wid = tid >> 5;
    const int wm = wid >> 1, wn = wid & 1;        // 4 x 2 warp grid, warp 64x64
    const int m0 = blockIdx.y * 256, n0 = blockIdx.x * 128;

    float acc[4][8][4];
    #pragma unroll
    for (int i = 0; i < 4; i++)
        #pragma unroll
        for (int j = 0; j < 8; j++)
            #pragma unroll
            for (int q = 0; q < 4; q++) acc[i][j][q] = 0.0f;

    #pragma unroll
    for (int s = 0; s < NSTAGE; s++) {
        fill_stage(sb + (uint32_t)s * STAGE_BYTES, A, B, m0, n0, s * KT, tid);
        CP_COMMIT();
    }

    const uint32_t a_base = (uint32_t)((wm * 64 + ((lane >> 3) & 1) * 8 + (lane & 7)) * ROWB
                                       + (lane >> 4) * 16);
    const uint32_t b_base = (uint32_t)((wn * 64 + ((lane >> 4) & 1) * 8 + (lane & 7)) * ROWB
                                       + ((lane >> 3) & 1) * 16);

    const int NITER = CCH / KT;   // 16
    for (int ks = 0; ks < NITER; ks++) {
        uint32_t st = sb + (uint32_t)(ks % NSTAGE) * STAGE_BYTES;
        if (ks < NITER - 3)      CP_WAIT(3);
        else if (ks == NITER-3)  CP_WAIT(2);
        else if (ks == NITER-2)  CP_WAIT(1);
        else                     CP_WAIT(0);
        __syncthreads();

        #pragma unroll
        for (int kk = 0; kk < KT; kk += 16) {
            uint32_t ah[4][4], bf[8][2];
            #pragma unroll
            for (int mt = 0; mt < 4; mt++) {
                uint32_t a = st + OFF_A + a_base + (uint32_t)(mt * 16 * ROWB + kk * 2);
                LDSM4(ah[mt][0], ah[mt][1], ah[mt][2], ah[mt][3], a);
            }
            #pragma unroll
            for (int pnt = 0; pnt < 4; pnt++) {
                uint32_t b = st + OFF_B + b_base + (uint32_t)(pnt * 16 * ROWB + kk * 2);
                LDSM4(bf[2*pnt][0], bf[2*pnt][1], bf[2*pnt+1][0], bf[2*pnt+1][1], b);
            }
            #pragma unroll
            for (int mt = 0; mt < 4; mt++)
                #pragma unroll
                for (int nt = 0; nt < 8; nt++)
                    MMAF16(acc[mt][nt], ah[mt], bf[nt]);
        }
        __syncthreads();
        if (ks + NSTAGE < NITER) {
            fill_stage(st, A, B, m0, n0, (ks + NSTAGE) * KT, tid);
            CP_COMMIT();
        }
    }

    // epilogue with fused activation
    #pragma unroll
    for (int mt = 0; mt < 4; mt++)
        #pragma unroll
        for (int nt = 0; nt < 8; nt++) {
            int row = m0 + wm * 64 + mt * 16 + (lane >> 2);
            int col = n0 + wn * 64 + nt * 8 + (lane & 3) * 2;
            float v0 = acc[mt][nt][0], v1 = acc[mt][nt][1];
            float v2 = acc[mt][nt][2], v3 = acc[mt][nt][3];
            if (act == 1) {
                v0 = 1.0f / (1.0f + __expf(-v0)); v1 = 1.0f / (1.0f + __expf(-v1));
                v2 = 1.0f / (1.0f + __expf(-v2)); v3 = 1.0f / (1.0f + __expf(-v3));
            } else if (act == 2) {
                v0 = __expf(v0); v1 = __expf(v1); v2 = __expf(v2); v3 = __expf(v3);
            }
            *(float2*)&out[(size_t)row * CCH + col]       = make_float2(v0, v1);
            *(float2*)&out[(size_t)(row + 8) * CCH + col] = make_float2(v2, v3);
        }
}

// ---------- chunked scan ----------
__global__ void scan_p1(const float* __restrict__ td){
    int bj = blockIdx.x, c = threadIdx.x;
    float dec = __expf(td[c]);
    size_t base = ((size_t)(bj / NCHUNK) * TT + (size_t)(bj % NCHUNK) * CHUNK_L) * CCH + c;
    float a = 0.0f;
    #pragma unroll 4
    for (int t = 0; t < CHUNK_L; t++)
        a = a * dec + g_k[base + (size_t)t * CCH] * g_v[base + (size_t)t * CCH];
    g_carry[(size_t)bj * CCH + c] = a;
}
__global__ void scan_p2(const float* __restrict__ td, const float* __restrict__ st){
    int b = blockIdx.x, c = threadIdx.x;
    float dL = __expf((float)CHUNK_L * td[c]);
    float s = st[b * CCH + c];
    for (int j = 0; j < NCHUNK; j++) {
        size_t o = (size_t)(b * NCHUNK + j) * CCH + c;
        g_sin[o] = s;
        s = s * dL + g_carry[o];
    }
}
__global__ void scan_p3(const float* __restrict__ td){
    int bj = blockIdx.x, c = threadIdx.x;
    float dec = __expf(td[c]);
    size_t base = ((size_t)(bj / NCHUNK) * TT + (size_t)(bj % NCHUNK) * CHUNK_L) * CCH + c;
    float s = g_sin[(size_t)bj * CCH + c];
    #pragma unroll 4
    for (int t = 0; t < CHUNK_L; t++) {
        size_t i = base + (size_t)t * CCH;
        s = s * dec + g_k[i] * g_v[i];
        g_of[i] = __float2half_rn(g_r[i] * s);
    }
}
__global__ void state_k(const float* __restrict__ x, float* __restrict__ dst){
    int i = blockIdx.x * 256 + threadIdx.x;
    if (i < BB * CCH)
        dst[i] = x[((size_t)(i >> 10) * TT + (TT - 1)) * CCH + (i & (CCH - 1))];
}

// ---------- host ----------
#define SYMADDR(var, p) do { void* _t; cudaGetSymbolAddress(&_t, var); p = _t; } while(0)

extern "C" void kernel_launch(void* const* d_in, const int* in_sizes, int n_in,
                              void* d_out, int out_size) {
    const float* x   = (const float*)d_in[0];
    const float* st  = (const float*)d_in[1];
    const float* Wr  = (const float*)d_in[2];
    const float* Wk  = (const float*)d_in[3];
    const float* Wv  = (const float*)d_in[4];
    const float* Wo  = (const float*)d_in[5];
    const float* tmr = (const float*)d_in[6];
    const float* tmk = (const float*)d_in[7];
    const float* tmv = (const float*)d_in[8];
    const float* td  = (const float*)d_in[9];
    float* dout = (float*)d_out;

    void *rin, *kin, *vin, *pr, *pk, *pv, *of, *wr, *wk, *wv, *wo;
    SYMADDR(g_rin, rin); SYMADDR(g_kin, kin); SYMADDR(g_vin, vin);
    SYMADDR(g_r, pr); SYMADDR(g_k, pk); SYMADDR(g_v, pv);
    SYMADDR(g_of, of);
    SYMADDR(g_Wr, wr); SYMADDR(g_Wk, wk); SYMADDR(g_Wv, wv); SYMADDR(g_Wo, wo);

    cudaFuncSetAttribute(gemm_half, cudaFuncAttributeMaxDynamicSharedMemorySize, GEMM_SMEM);

    CvtBatch cb;
    cb.src[0] = Wr; cb.dst[0] = (__half*)wr;
    cb.src[1] = Wk; cb.dst[1] = (__half*)wk;
    cb.src[2] = Wv; cb.dst[2] = (__half*)wv;
    cb.src[3] = Wo; cb.dst[3] = (__half*)wo;
    dim3 cg(CCH * CCH / 1024, 4);
    cvt_w_k<<<cg, 256>>>(cb);
    prep_k<<<NELEM / 256, 256>>>(x, st, tmr, tmk, tmv);

    GemmBatch gb;
    gb.a[0] = (const __half*)rin; gb.b[0] = (const __half*)wr;
    gb.out[0] = (float*)pr; gb.act[0] = 1;
    gb.a[1] = (const __half*)kin; gb.b[1] = (const __half*)wk;
    gb.out[1] = (float*)pk; gb.act[1] = 2;
    gb.a[2] = (const __half*)vin; gb.b[2] = (const __half*)wv;
    gb.out[2] = (float*)pv; gb.act[2] = 0;

    dim3 gg(CCH / 128, MTOT / 256, 3);   // (8, 64, 3)
    gemm_half<<<gg, 256, GEMM_SMEM>>>(gb);

    scan_p1<<<BB * NCHUNK, CCH>>>(td);
    scan_p2<<<BB, CCH>>>(td, st);
    scan_p3<<<BB * NCHUNK, CCH>>>(td);

    GemmBatch go;
    go.a[0] = (const __half*)of; go.b[0] = (const __half*)wo;
    go.out[0] = dout; go.act[0] = 0;
    go.a[1] = go.a[0]; go.b[1] = go.b[0]; go.out[1] = dout; go.act[1] = 0;
    go.a[2] = go.a[0]; go.b[2] = go.b[0]; go.out[2] = dout; go.act[2] = 0;

    dim3 g1(CCH / 128, MTOT / 256, 1);
    gemm_half<<<g1, 256, GEMM_SMEM>>>(go);

    if (out_size >= NELEM + BB * CCH)
        state_k<<<(BB * CCH + 255) / 256, 256>>>(x, dout + NELEM);
}

// round 11
// speedup vs baseline: 2.6728x; 1.1525x over previous
#include <cuda_runtime.h>
#include <cuda_fp16.h>
#include <cstdint>

#define BB 4
#define TT 4096
#define CCH 1024
#define MTOT (BB*TT)
#define NELEM (MTOT*CCH)
#define NCHUNK 64
#define CHUNK_L (TT/NCHUNK)

// GEMM: CTA 128x128, KT=64, 256 thr = 8 warps (2M x 4N), warp 64x32, 2 CTA/SM
#define KT 64
#define ROWB 144                    // 64 fp16 (128B) + 16B pad
#define A_BYTES (128*ROWB)          // 18432
#define B_BYTES (128*ROWB)          // 18432
#define OFF_A  0
#define OFF_B  A_BYTES
#define STAGE_BYTES (A_BYTES + B_BYTES)       // 36864
#define NSTAGE 3
#define GEMM_SMEM (NSTAGE*STAGE_BYTES)        // 110592

// ---------- scratch ----------
__device__ __half g_rin[NELEM], g_kin[NELEM], g_vin[NELEM];
__device__ __half g_r[NELEM], g_k[NELEM], g_v[NELEM];
__device__ __half g_of[NELEM];
__device__ __half g_Wr[CCH*CCH], g_Wk[CCH*CCH], g_Wv[CCH*CCH], g_Wo[CCH*CCH];
__device__ float g_carry[BB*NCHUNK*CCH];
__device__ float g_sin[BB*NCHUNK*CCH];

// ---------- helpers ----------
static __device__ __forceinline__ uint32_t smem_u32(const void* p){
    uint32_t a;
    asm("{ .reg .u64 t; cvta.to.shared.u64 t, %1; cvt.u32.u64 %0, t; }" : "=r"(a) : "l"(p));
    return a;
}
static __device__ __forceinline__ void cp16(uint32_t s, const void* g){
    asm volatile("cp.async.cg.shared.global [%0], [%1], 16;" :: "r"(s), "l"(g) : "memory");
}
#define CP_COMMIT() asm volatile("cp.async.commit_group;" ::: "memory")
#define CP_WAIT(n)  asm volatile("cp.async.wait_group %0;" :: "n"(n) : "memory")

#define LDSM4(r0,r1,r2,r3,a) \
    asm volatile("ldmatrix.sync.aligned.m8n8.x4.shared.b16 {%0,%1,%2,%3}, [%4];" \
        : "=r"(r0),"=r"(r1),"=r"(r2),"=r"(r3) : "r"(a))

#define MMAF16(c, a, b) \
    asm volatile("mma.sync.aligned.m16n8k16.row.col.f32.f16.f16.f32 " \
        "{%0,%1,%2,%3}, {%4,%5,%6,%7}, {%8,%9}, {%0,%1,%2,%3};" \
        : "+f"((c)[0]),"+f"((c)[1]),"+f"((c)[2]),"+f"((c)[3]) \
        : "r"((a)[0]),"r"((a)[1]),"r"((a)[2]),"r"((a)[3]), "r"((b)[0]),"r"((b)[1]))

// ---------- prep ----------
struct CvtBatch { const float* src[4]; __half* dst[4]; };
__global__ void cvt_w_k(CvtBatch p){
    int i = blockIdx.x * 256 + threadIdx.x;
    const float* s = p.src[blockIdx.y];
    __half* d = p.dst[blockIdx.y];
    float4 v = *(const float4*)&s[i * 4];
    *(__half2*)&d[i * 4]     = __floats2half2_rn(v.x, v.y);
    *(__half2*)&d[i * 4 + 2] = __floats2half2_rn(v.z, v.w);
}
__global__ void prep_k(const float* __restrict__ x, const float* __restrict__ st,
                       const float* __restrict__ tmr, const float* __restrict__ tmk,
                       const float* __restrict__ tmv){
    int i = blockIdx.x * 256 + threadIdx.x;
    int c = i & (CCH - 1);
    int bt = i >> 10;
    int t = bt & (TT - 1);
    float xv = x[i];
    float xm = (t == 0) ? st[(bt >> 12) * CCH + c] : x[i - CCH];
    float mr = tmr[c], mk = tmk[c], mv = tmv[c];
    g_rin[i] = __float2half_rn(xv * mr + xm * (1.0f - mr));
    g_kin[i] = __float2half_rn(xv * mk + xm * (1.0f - mk));
    g_vin[i] = __float2half_rn(xv * mv + xm * (1.0f - mv));
}

// ---------- GEMM: out[m,n] = sum_c A[m,c]*W[n,c] ----------
struct GemmBatch {
    const __half *a[3], *b[3];
    void* out[3];
    int act[3];
    int ishalf[3];
};

static __device__ __forceinline__ void fill_stage(uint32_t st,
        const __half* __restrict__ A, const __half* __restrict__ B,
        int m0, int n0, int k0, int tid){
    #pragma unroll
    for (int i = 0; i < 4; i++) {           // A: 128 rows x 8 chunks of 8 fp16
        int idx = tid + i * 256;
        int r = idx >> 3, ch = idx & 7;
        cp16(st + OFF_A + (uint32_t)(r * ROWB + ch * 16),
             A + (size_t)(m0 + r) * CCH + k0 + ch * 8);
    }
    #pragma unroll
    for (int i = 0; i < 4; i++) {           // B: 128 rows x 8 chunks
        int idx = tid + i * 256;
        int r = idx >> 3, ch = idx & 7;
        cp16(st + OFF_B + (uint32_t)(r * ROWB + ch * 16),
             B + (size_t)(n0 + r) * CCH + k0 + ch * 8);
    }
}

__global__ void __launch_bounds__(256, 2)
gemm_half(GemmBatch p){
    extern __shared__ __align__(16) char smem[];
    uint32_t sb = smem_u32(smem);
    const int z = blockIdx.z;
    const __half* __restrict__ A = p.a[z];
    const __half* __restrict__ B = p.b[z];
    const int act = p.act[z];
    const int ishalf = p.ishalf[z];

    const int tid = threadIdx.x, lane = tid & 31, wid = tid >> 5;
    const int wm = wid >> 2, wn = wid & 3;        // 2 x 4 warp grid, warp 64x32
    const int m0 = blockIdx.y * 128, n0 = blockIdx.x * 128;

    float acc[4][4][4];
    #pragma unroll
    for (int i = 0; i < 4; i++)
        #pragma unroll
        for (int j = 0; j < 4; j++)
            #pragma unroll
            for (int q = 0; q < 4; q++) acc[i][j][q] = 0.0f;

    #pragma unroll
    for (int s = 0; s < NSTAGE; s++) {
        fill_stage(sb + (uint32_t)s * STAGE_BYTES, A, B, m0, n0, s * KT, tid);
        CP_COMMIT();
    }

    const uint32_t a_base = (uint32_t)((wm * 64 + ((lane >> 3) & 1) * 8 + (lane & 7)) * ROWB
                                       + (lane >> 4) * 16);
    const uint32_t b_base = (uint32_t)((wn * 32 + ((lane >> 4) & 1) * 8 + (lane & 7)) * ROWB
                                       + ((lane >> 3) & 1) * 16);

    const int NITER = CCH / KT;   // 16
    for (int ks = 0; ks < NITER; ks++) {
        uint32_t st = sb + (uint32_t)(ks % NSTAGE) * STAGE_BYTES;
        if (ks < NITER - 2)      CP_WAIT(2);
        else if (ks == NITER-2)  CP_WAIT(1);
        else                     CP_WAIT(0);
        __syncthreads();

        #pragma unroll
        for (int kk = 0; kk < KT; kk += 16) {
            uint32_t ah[4][4], bf[4][2];
            #pragma unroll
            for (int mt = 0; mt < 4; mt++) {
                uint32_t a = st + OFF_A + a_base + (uint32_t)(mt * 16 * ROWB + kk * 2);
                LDSM4(ah[mt][0], ah[mt][1], ah[mt][2], ah[mt][3], a);
            }
            #pragma unroll
            for (int pnt = 0; pnt < 2; pnt++) {
                uint32_t b = st + OFF_B + b_base + (uint32_t)(pnt * 16 * ROWB + kk * 2);
                LDSM4(bf[2*pnt][0], bf[2*pnt][1], bf[2*pnt+1][0], bf[2*pnt+1][1], b);
            }
            #pragma unroll
            for (int mt = 0; mt < 4; mt++)
                #pragma unroll
                for (int nt = 0; nt < 4; nt++)
                    MMAF16(acc[mt][nt], ah[mt], bf[nt]);
        }
        __syncthreads();
        if (ks + NSTAGE < NITER) {
            fill_stage(st, A, B, m0, n0, (ks + NSTAGE) * KT, tid);
            CP_COMMIT();
        }
    }

    // epilogue with fused activation
    #pragma unroll
    for (int mt = 0; mt < 4; mt++)
        #pragma unroll
        for (int nt = 0; nt < 4; nt++) {
            int row = m0 + wm * 64 + mt * 16 + (lane >> 2);
            int col = n0 + wn * 32 + nt * 8 + (lane & 3) * 2;
            float v0 = acc[mt][nt][0], v1 = acc[mt][nt][1];
            float v2 = acc[mt][nt][2], v3 = acc[mt][nt][3];
            if (act == 1) {
                v0 = 1.0f / (1.0f + __expf(-v0)); v1 = 1.0f / (1.0f + __expf(-v1));
                v2 = 1.0f / (1.0f + __expf(-v2)); v3 = 1.0f / (1.0f + __expf(-v3));
            } else if (act == 2) {
                v0 = __expf(v0); v1 = __expf(v1); v2 = __expf(v2); v3 = __expf(v3);
            }
            if (ishalf) {
                __half* o = (__half*)p.out[z];
                *(__half2*)&o[(size_t)row * CCH + col]       = __floats2half2_rn(v0, v1);
                *(__half2*)&o[(size_t)(row + 8) * CCH + col] = __floats2half2_rn(v2, v3);
            } else {
                float* o = (float*)p.out[z];
                *(float2*)&o[(size_t)row * CCH + col]       = make_float2(v0, v1);
                *(float2*)&o[(size_t)(row + 8) * CCH + col] = make_float2(v2, v3);
            }
        }
}

// ---------- chunked scan ----------
__global__ void scan_p1(const float* __restrict__ td){
    int bj = blockIdx.x, c = threadIdx.x;
    float dec = __expf(td[c]);
    size_t base = ((size_t)(bj / NCHUNK) * TT + (size_t)(bj % NCHUNK) * CHUNK_L) * CCH + c;
    float a = 0.0f;
    #pragma unroll 8
    for (int t = 0; t < CHUNK_L; t++)
        a = a * dec + __half2float(g_k[base + (size_t)t * CCH]) *
                      __half2float(g_v[base + (size_t)t * CCH]);
    g_carry[(size_t)bj * CCH + c] = a;
}
__global__ void scan_p2(const float* __restrict__ td, const float* __restrict__ st){
    int b = blockIdx.x, c = threadIdx.x;
    float dL = __expf((float)CHUNK_L * td[c]);
    float s = st[b * CCH + c];
    for (int j = 0; j < NCHUNK; j++) {
        size_t o = (size_t)(b * NCHUNK + j) * CCH + c;
        g_sin[o] = s;
        s = s * dL + g_carry[o];
    }
}
__global__ void scan_p3(const float* __restrict__ td){
    int bj = blockIdx.x, c = threadIdx.x;
    float dec = __expf(td[c]);
    size_t base = ((size_t)(bj / NCHUNK) * TT + (size_t)(bj % NCHUNK) * CHUNK_L) * CCH + c;
    float s = g_sin[(size_t)bj * CCH + c];
    #pragma unroll 4
    for (int t = 0; t < CHUNK_L; t++) {
        size_t i = base + (size_t)t * CCH;
        s = s * dec + __half2float(g_k[i]) * __half2float(g_v[i]);
        g_of[i] = __float2half_rn(__half2float(g_r[i]) * s);
    }
}
__global__ void state_k(const float* __restrict__ x, float* __restrict__ dst){
    int i = blockIdx.x * 256 + threadIdx.x;
    if (i < BB * CCH)
        dst[i] = x[((size_t)(i >> 10) * TT + (TT - 1)) * CCH + (i & (CCH - 1))];
}

// ---------- host ----------
#define SYMADDR(var, p) do { void* _t; cudaGetSymbolAddress(&_t, var); p = _t; } while(0)

extern "C" void kernel_launch(void* const* d_in, const int* in_sizes, int n_in,
                              void* d_out, int out_size) {
    const float* x   = (const float*)d_in[0];
    const float* st  = (const float*)d_in[1];
    const float* Wr  = (const float*)d_in[2];
    const float* Wk  = (const float*)d_in[3];
    const float* Wv  = (const float*)d_in[4];
    const float* Wo  = (const float*)d_in[5];
    const float* tmr = (const float*)d_in[6];
    const float* tmk = (const float*)d_in[7];
    const float* tmv = (const float*)d_in[8];
    const float* td  = (const float*)d_in[9];
    float* dout = (float*)d_out;

    void *rin, *kin, *vin, *pr, *pk, *pv, *of, *wr, *wk, *wv, *wo;
    SYMADDR(g_rin, rin); SYMADDR(g_kin, kin); SYMADDR(g_vin, vin);
    SYMADDR(g_r, pr); SYMADDR(g_k, pk); SYMADDR(g_v, pv);
    SYMADDR(g_of, of);
    SYMADDR(g_Wr, wr); SYMADDR(g_Wk, wk); SYMADDR(g_Wv, wv); SYMADDR(g_Wo, wo);

    cudaFuncSetAttribute(gemm_half, cudaFuncAttributeMaxDynamicSharedMemorySize, GEMM_SMEM);

    CvtBatch cb;
    cb.src[0] = Wr; cb.dst[0] = (__half*)wr;
    cb.src[1] = Wk; cb.dst[1] = (__half*)wk;
    cb.src[2] = Wv; cb.dst[2] = (__half*)wv;
    cb.src[3] = Wo; cb.dst[3] = (__half*)wo;
    dim3 cg(CCH * CCH / 1024, 4);
    cvt_w_k<<<cg, 256>>>(cb);
    prep_k<<<NELEM / 256, 256>>>(x, st, tmr, tmk, tmv);

    GemmBatch gb;
    gb.a[0] = (const __half*)rin; gb.b[0] = (const __half*)wr;
    gb.out[0] = pr; gb.act[0] = 1; gb.ishalf[0] = 1;
    gb.a[1] = (const __half*)kin; gb.b[1] = (const __half*)wk;
    gb.out[1] = pk; gb.act[1] = 2; gb.ishalf[1] = 1;
    gb.a[2] = (const __half*)vin; gb.b[2] = (const __half*)wv;
    gb.out[2] = pv; gb.act[2] = 0; gb.ishalf[2] = 1;

    dim3 gg(CCH / 128, MTOT / 128, 3);   // (8, 128, 3)
    gemm_half<<<gg, 256, GEMM_SMEM>>>(gb);

    scan_p1<<<BB * NCHUNK, CCH>>>(td);
    scan_p2<<<BB, CCH>>>(td, st);
    scan_p3<<<BB * NCHUNK, CCH>>>(td);

    GemmBatch go;
    go.a[0] = (const __half*)of; go.b[0] = (const __half*)wo;
    go.out[0] = dout; go.act[0] = 0; go.ishalf[0] = 0;
    go.a[1] = go.a[0]; go.b[1] = go.b[0]; go.out[1] = dout; go.act[1] = 0; go.ishalf[1] = 0;
    go.a[2] = go.a[0]; go.b[2] = go.b[0]; go.out[2] = dout; go.act[2] = 0; go.ishalf[2] = 0;

    dim3 g1(CCH / 128, MTOT / 128, 1);   // (8, 128, 1)
    gemm_half<<<g1, 256, GEMM_SMEM>>>(go);

    if (out_size >= NELEM + BB * CCH)
        state_k<<<(BB * CCH + 255) / 256, 256>>>(x, dout + NELEM);
}

// round 12
// speedup vs baseline: 2.8281x; 1.0581x over previous
#include <cuda_runtime.h>
#include <cuda_fp16.h>
#include <cstdint>

#define BB 4
#define TT 4096
#define CCH 1024
#define MTOT (BB*TT)
#define NELEM (MTOT*CCH)
#define NCHUNK 64
#define CHUNK_L (TT/NCHUNK)

// GEMM: CTA 128x128, KT=64, 256 thr = 8 warps (2M x 4N), warp 64x32, 2 CTA/SM
#define KT 64
#define ROWB 144                    // 64 fp16 (128B) + 16B pad
#define A_BYTES (128*ROWB)
#define B_BYTES (128*ROWB)
#define OFF_A  0
#define OFF_B  A_BYTES
#define STAGE_BYTES (A_BYTES + B_BYTES)       // 36864
#define NSTAGE 3
#define GEMM_SMEM (NSTAGE*STAGE_BYTES)        // 110592

// ---------- scratch ----------
__device__ __half g_rin[NELEM], g_kin[NELEM], g_vin[NELEM];
__device__ __half g_r[NELEM], g_k[NELEM], g_v[NELEM];
__device__ __half g_of[NELEM];
__device__ __half g_Wr[CCH*CCH], g_Wk[CCH*CCH], g_Wv[CCH*CCH], g_Wo[CCH*CCH];
__device__ float g_carry[BB*NCHUNK*CCH];
__device__ float g_sin[BB*NCHUNK*CCH];

// ---------- helpers ----------
static __device__ __forceinline__ uint32_t smem_u32(const void* p){
    uint32_t a;
    asm("{ .reg .u64 t; cvta.to.shared.u64 t, %1; cvt.u32.u64 %0, t; }" : "=r"(a) : "l"(p));
    return a;
}
static __device__ __forceinline__ void cp16(uint32_t s, const void* g){
    asm volatile("cp.async.cg.shared.global [%0], [%1], 16;" :: "r"(s), "l"(g) : "memory");
}
#define CP_COMMIT() asm volatile("cp.async.commit_group;" ::: "memory")
#define CP_WAIT(n)  asm volatile("cp.async.wait_group %0;" :: "n"(n) : "memory")

#define LDSM4(r0,r1,r2,r3,a) \
    asm volatile("ldmatrix.sync.aligned.m8n8.x4.shared.b16 {%0,%1,%2,%3}, [%4];" \
        : "=r"(r0),"=r"(r1),"=r"(r2),"=r"(r3) : "r"(a))

#define MMAF16(c, a, b) \
    asm volatile("mma.sync.aligned.m16n8k16.row.col.f32.f16.f16.f32 " \
        "{%0,%1,%2,%3}, {%4,%5,%6,%7}, {%8,%9}, {%0,%1,%2,%3};" \
        : "+f"((c)[0]),"+f"((c)[1]),"+f"((c)[2]),"+f"((c)[3]) \
        : "r"((a)[0]),"r"((a)[1]),"r"((a)[2]),"r"((a)[3]), "r"((b)[0]),"r"((b)[1]))

// ---------- prep ----------
struct CvtBatch { const float* src[4]; __half* dst[4]; };
__global__ void cvt_w_k(CvtBatch p){
    int i = blockIdx.x * 256 + threadIdx.x;
    const float* s = p.src[blockIdx.y];
    __half* d = p.dst[blockIdx.y];
    float4 v = *(const float4*)&s[i * 4];
    *(__half2*)&d[i * 4]     = __floats2half2_rn(v.x, v.y);
    *(__half2*)&d[i * 4 + 2] = __floats2half2_rn(v.z, v.w);
}
__global__ void prep_k(const float* __restrict__ x, const float* __restrict__ st,
                       const float* __restrict__ tmr, const float* __restrict__ tmk,
                       const float* __restrict__ tmv){
    int e = blockIdx.x * 256 + threadIdx.x;   // pair index
    int i = e * 2;
    int c = i & (CCH - 1);
    int bt = i >> 10;
    int t = bt & (TT - 1);
    float2 xv = *(const float2*)&x[i];
    float2 xm;
    if (t == 0) xm = *(const float2*)&st[(bt >> 12) * CCH + c];
    else        xm = *(const float2*)&x[i - CCH];
    float2 mr = *(const float2*)&tmr[c];
    float2 mk = *(const float2*)&tmk[c];
    float2 mv = *(const float2*)&tmv[c];
    *(__half2*)&g_rin[i] = __floats2half2_rn(xv.x * mr.x + xm.x * (1.0f - mr.x),
                                             xv.y * mr.y + xm.y * (1.0f - mr.y));
    *(__half2*)&g_kin[i] = __floats2half2_rn(xv.x * mk.x + xm.x * (1.0f - mk.x),
                                             xv.y * mk.y + xm.y * (1.0f - mk.y));
    *(__half2*)&g_vin[i] = __floats2half2_rn(xv.x * mv.x + xm.x * (1.0f - mv.x),
                                             xv.y * mv.y + xm.y * (1.0f - mv.y));
}

// ---------- GEMM: out[m,n] = sum_c A[m,c]*W[n,c] ----------
struct GemmBatch {
    const __half *a[3], *b[3];
    void* out[3];
    int act[3];
    int ishalf[3];
};

static __device__ __forceinline__ void fill_stage(uint32_t st,
        const __half* __restrict__ A, const __half* __restrict__ B,
        int m0, int n0, int k0, int tid){
    #pragma unroll
    for (int i = 0; i < 4; i++) {
        int idx = tid + i * 256;
        int r = idx >> 3, ch = idx & 7;
        cp16(st + OFF_A + (uint32_t)(r * ROWB + ch * 16),
             A + (size_t)(m0 + r) * CCH + k0 + ch * 8);
    }
    #pragma unroll
    for (int i = 0; i < 4; i++) {
        int idx = tid + i * 256;
        int r = idx >> 3, ch = idx & 7;
        cp16(st + OFF_B + (uint32_t)(r * ROWB + ch * 16),
             B + (size_t)(n0 + r) * CCH + k0 + ch * 8);
    }
}

__global__ void __launch_bounds__(256, 2)
gemm_half(GemmBatch p){
    extern __shared__ __align__(16) char smem[];
    uint32_t sb = smem_u32(smem);
    const int z = blockIdx.z;
    const __half* __restrict__ A = p.a[z];
    const __half* __restrict__ B = p.b[z];
    const int act = p.act[z];
    const int ishalf = p.ishalf[z];

    const int tid = threadIdx.x, lane = tid & 31, wid = tid >> 5;
    const int wm = wid >> 2, wn = wid & 3;        // 2 x 4 warp grid, warp 64x32
    const int m0 = blockIdx.y * 128, n0 = blockIdx.x * 128;

    float acc[4][4][4];
    #pragma unroll
    for (int i = 0; i < 4; i++)
        #pragma unroll
        for (int j = 0; j < 4; j++)
            #pragma unroll
            for (int q = 0; q < 4; q++) acc[i][j][q] = 0.0f;

    // prologue: fill stages 0,1
    #pragma unroll
    for (int s = 0; s < 2; s++) {
        fill_stage(sb + (uint32_t)s * STAGE_BYTES, A, B, m0, n0, s * KT, tid);
        CP_COMMIT();
    }

    const uint32_t a_base = (uint32_t)((wm * 64 + ((lane >> 3) & 1) * 8 + (lane & 7)) * ROWB
                                       + (lane >> 4) * 16);
    const uint32_t b_base = (uint32_t)((wn * 32 + ((lane >> 4) & 1) * 8 + (lane & 7)) * ROWB
                                       + ((lane >> 3) & 1) * 16);

    const int NITER = CCH / KT;   // 16
    for (int ks = 0; ks < NITER; ks++) {
        uint32_t st = sb + (uint32_t)(ks % NSTAGE) * STAGE_BYTES;
        if (ks < NITER - 1) CP_WAIT(1);
        else                CP_WAIT(0);
        __syncthreads();
        // fill stage ks+2 into buffer (ks+2)%3 = (ks-1)%3, freed by the sync above;
        // copies land while this iteration's MMAs run.
        if (ks + 2 < NITER) {
            fill_stage(sb + (uint32_t)((ks + 2) % NSTAGE) * STAGE_BYTES,
                       A, B, m0, n0, (ks + 2) * KT, tid);
            CP_COMMIT();
        }

        #pragma unroll
        for (int kk = 0; kk < KT; kk += 16) {
            uint32_t ah[4][4], bf[4][2];
            #pragma unroll
            for (int mt = 0; mt < 4; mt++) {
                uint32_t a = st + OFF_A + a_base + (uint32_t)(mt * 16 * ROWB + kk * 2);
                LDSM4(ah[mt][0], ah[mt][1], ah[mt][2], ah[mt][3], a);
            }
            #pragma unroll
            for (int pnt = 0; pnt < 2; pnt++) {
                uint32_t b = st + OFF_B + b_base + (uint32_t)(pnt * 16 * ROWB + kk * 2);
                LDSM4(bf[2*pnt][0], bf[2*pnt][1], bf[2*pnt+1][0], bf[2*pnt+1][1], b);
            }
            #pragma unroll
            for (int mt = 0; mt < 4; mt++)
                #pragma unroll
                for (int nt = 0; nt < 4; nt++)
                    MMAF16(acc[mt][nt], ah[mt], bf[nt]);
        }
    }

    // epilogue with fused activation
    #pragma unroll
    for (int mt = 0; mt < 4; mt++)
        #pragma unroll
        for (int nt = 0; nt < 4; nt++) {
            int row = m0 + wm * 64 + mt * 16 + (lane >> 2);
            int col = n0 + wn * 32 + nt * 8 + (lane & 3) * 2;
            float v0 = acc[mt][nt][0], v1 = acc[mt][nt][1];
            float v2 = acc[mt][nt][2], v3 = acc[mt][nt][3];
            if (act == 1) {
                v0 = 1.0f / (1.0f + __expf(-v0)); v1 = 1.0f / (1.0f + __expf(-v1));
                v2 = 1.0f / (1.0f + __expf(-v2)); v3 = 1.0f / (1.0f + __expf(-v3));
            } else if (act == 2) {
                v0 = __expf(v0); v1 = __expf(v1); v2 = __expf(v2); v3 = __expf(v3);
            }
            if (ishalf) {
                __half* o = (__half*)p.out[z];
                *(__half2*)&o[(size_t)row * CCH + col]       = __floats2half2_rn(v0, v1);
                *(__half2*)&o[(size_t)(row + 8) * CCH + col] = __floats2half2_rn(v2, v3);
            } else {
                float* o = (float*)p.out[z];
                *(float2*)&o[(size_t)row * CCH + col]       = make_float2(v0, v1);
                *(float2*)&o[(size_t)(row + 8) * CCH + col] = make_float2(v2, v3);
            }
        }
}

// ---------- chunked scan (each thread: 2 channels via half2) ----------
__global__ void scan_p1(const float* __restrict__ td){
    int bj = blockIdx.x, c2 = threadIdx.x;     // 512 threads, channels 2c2, 2c2+1
    int c = c2 * 2;
    float2 tdv = *(const float2*)&td[c];
    float d0 = __expf(tdv.x), d1 = __expf(tdv.y);
    size_t base = ((size_t)(bj / NCHUNK) * TT + (size_t)(bj % NCHUNK) * CHUNK_L) * CCH + c;
    float a0 = 0.0f, a1 = 0.0f;
    #pragma unroll 8
    for (int t = 0; t < CHUNK_L; t++) {
        size_t i = base + (size_t)t * CCH;
        float2 kk = __half22float2(*(const __half2*)&g_k[i]);
        float2 vv = __half22float2(*(const __half2*)&g_v[i]);
        a0 = a0 * d0 + kk.x * vv.x;
        a1 = a1 * d1 + kk.y * vv.y;
    }
    *(float2*)&g_carry[(size_t)bj * CCH + c] = make_float2(a0, a1);
}
__global__ void scan_p2(const float* __restrict__ td, const float* __restrict__ st){
    int b = blockIdx.x, c = threadIdx.x;
    float dL = __expf((float)CHUNK_L * td[c]);
    float s = st[b * CCH + c];
    for (int j = 0; j < NCHUNK; j++) {
        size_t o = (size_t)(b * NCHUNK + j) * CCH + c;
        g_sin[o] = s;
        s = s * dL + g_carry[o];
    }
}
__global__ void scan_p3(const float* __restrict__ td){
    int bj = blockIdx.x, c2 = threadIdx.x;
    int c = c2 * 2;
    float2 tdv = *(const float2*)&td[c];
    float d0 = __expf(tdv.x), d1 = __expf(tdv.y);
    size_t base = ((size_t)(bj / NCHUNK) * TT + (size_t)(bj % NCHUNK) * CHUNK_L) * CCH + c;
    float2 s = *(const float2*)&g_sin[(size_t)bj * CCH + c];
    #pragma unroll 4
    for (int t = 0; t < CHUNK_L; t++) {
        size_t i = base + (size_t)t * CCH;
        float2 kk = __half22float2(*(const __half2*)&g_k[i]);
        float2 vv = __half22float2(*(const __half2*)&g_v[i]);
        float2 rr = __half22float2(*(const __half2*)&g_r[i]);
        s.x = s.x * d0 + kk.x * vv.x;
        s.y = s.y * d1 + kk.y * vv.y;
        *(__half2*)&g_of[i] = __floats2half2_rn(rr.x * s.x, rr.y * s.y);
    }
}
__global__ void state_k(const float* __restrict__ x, float* __restrict__ dst){
    int i = blockIdx.x * 256 + threadIdx.x;
    if (i < BB * CCH)
        dst[i] = x[((size_t)(i >> 10) * TT + (TT - 1)) * CCH + (i & (CCH - 1))];
}

// ---------- host ----------
#define SYMADDR(var, p) do { void* _t; cudaGetSymbolAddress(&_t, var); p = _t; } while(0)

extern "C" void kernel_launch(void* const* d_in, const int* in_sizes, int n_in,
                              void* d_out, int out_size) {
    const float* x   = (const float*)d_in[0];
    const float* st  = (const float*)d_in[1];
    const float* Wr  = (const float*)d_in[2];
    const float* Wk  = (const float*)d_in[3];
    const float* Wv  = (const float*)d_in[4];
    const float* Wo  = (const float*)d_in[5];
    const float* tmr = (const float*)d_in[6];
    const float* tmk = (const float*)d_in[7];
    const float* tmv = (const float*)d_in[8];
    const float* td  = (const float*)d_in[9];
    float* dout = (float*)d_out;

    void *rin, *kin, *vin, *pr, *pk, *pv, *of, *wr, *wk, *wv, *wo;
    SYMADDR(g_rin, rin); SYMADDR(g_kin, kin); SYMADDR(g_vin, vin);
    SYMADDR(g_r, pr); SYMADDR(g_k, pk); SYMADDR(g_v, pv);
    SYMADDR(g_of, of);
    SYMADDR(g_Wr, wr); SYMADDR(g_Wk, wk); SYMADDR(g_Wv, wv); SYMADDR(g_Wo, wo);

    cudaFuncSetAttribute(gemm_half, cudaFuncAttributeMaxDynamicSharedMemorySize, GEMM_SMEM);

    CvtBatch cb;
    cb.src[0] = Wr; cb.dst[0] = (__half*)wr;
    cb.src[1] = Wk; cb.dst[1] = (__half*)wk;
    cb.src[2] = Wv; cb.dst[2] = (__half*)wv;
    cb.src[3] = Wo; cb.dst[3] = (__half*)wo;
    dim3 cg(CCH * CCH / 1024, 4);
    cvt_w_k<<<cg, 256>>>(cb);
    prep_k<<<NELEM / 512, 256>>>(x, st, tmr, tmk, tmv);

    GemmBatch gb;
    gb.a[0] = (const __half*)rin; gb.b[0] = (const __half*)wr;
    gb.out[0] = pr; gb.act[0] = 1; gb.ishalf[0] = 1;
    gb.a[1] = (const __half*)kin; gb.b[1] = (const __half*)wk;
    gb.out[1] = pk; gb.act[1] = 2; gb.ishalf[1] = 1;
    gb.a[2] = (const __half*)vin; gb.b[2] = (const __half*)wv;
    gb.out[2] = pv; gb.act[2] = 0; gb.ishalf[2] = 1;

    dim3 gg(CCH / 128, MTOT / 128, 3);
    gemm_half<<<gg, 256, GEMM_SMEM>>>(gb);

    scan_p1<<<BB * NCHUNK, 512>>>(td);
    scan_p2<<<BB, CCH>>>(td, st);
    scan_p3<<<BB * NCHUNK, 512>>>(td);

    GemmBatch go;
    go.a[0] = (const __half*)of; go.b[0] = (const __half*)wo;
    go.out[0] = dout; go.act[0] = 0; go.ishalf[0] = 0;
    go.a[1] = go.a[0]; go.b[1] = go.b[0]; go.out[1] = dout; go.act[1] = 0; go.ishalf[1] = 0;
    go.a[2] = go.a[0]; go.b[2] = go.b[0]; go.out[2] = dout; go.act[2] = 0; go.ishalf[2] = 0;

    dim3 g1(CCH / 128, MTOT / 128, 1);
    gemm_half<<<g1, 256, GEMM_SMEM>>>(go);

    if (out_size >= NELEM + BB * CCH)
        state_k<<<(BB * CCH + 255) / 256, 256>>>(x, dout + NELEM);
}